// round 3
// baseline (speedup 1.0000x reference)
#include <cuda_runtime.h>
#include <cuda_bf16.h>
#include <math.h>
#include <stdint.h>

// Problem constants
#define S_LEN 1024
#define BATCH 2
#define DMODEL 1024
#define HEADS 16
#define HDIM 64
#define TLEN 2048
#define FFDIM 4096
#define ROWS_X (S_LEN * BATCH)     // 2048
#define ROWS_T (TLEN * BATCH)      // 4096

// ---------------- scratch buffers (device globals; no allocation allowed) ----
__device__ float g_q [ROWS_X * DMODEL];
__device__ float g_ke[ROWS_T * DMODEL];
__device__ float g_kr[ROWS_T * DMODEL];
__device__ float g_v [ROWS_T * DMODEL];
__device__ float g_av[ROWS_X * DMODEL];
__device__ float g_t [ROWS_X * DMODEL];
__device__ float g_u [ROWS_X * DMODEL];
__device__ float g_h1[ROWS_X * FFDIM];

// ---------------- tf32 tensor-core GEMM -------------------------------------
// C[M,N] = A[M,Kd] * W[N,Kd]^T (+bias)(+relu), blockIdx.z selects (W,C) pair.
// BM=BN=128, BK=32, 256 thr (8 warps, 2m x 4n), warp tile 64x32, mma m16n8k8.
// Double-buffered cp.async, XOR-swizzled smem (no pad), fp32 accum.

__device__ __forceinline__ uint32_t f2tf32(float f) {
    uint32_t r;
    asm("cvt.rna.tf32.f32 %0, %1;" : "=r"(r) : "f"(f));
    return r;
}

__device__ __forceinline__ void cp_async16(uint32_t saddr, const void* gptr) {
    asm volatile("cp.async.cg.shared.global [%0], [%1], 16;\n"
                 :: "r"(saddr), "l"(gptr));
}
__device__ __forceinline__ void cp_commit() {
    asm volatile("cp.async.commit_group;\n");
}
template <int N>
__device__ __forceinline__ void cp_wait() {
    asm volatile("cp.async.wait_group %0;\n" :: "n"(N));
}

__device__ __forceinline__ void mma_tf32(float* d, const uint32_t* a, const uint32_t* b) {
    asm volatile(
        "mma.sync.aligned.m16n8k8.row.col.f32.tf32.tf32.f32 "
        "{%0,%1,%2,%3}, {%4,%5,%6,%7}, {%8,%9}, {%0,%1,%2,%3};\n"
        : "+f"(d[0]), "+f"(d[1]), "+f"(d[2]), "+f"(d[3])
        : "r"(a[0]), "r"(a[1]), "r"(a[2]), "r"(a[3]), "r"(b[0]), "r"(b[1]));
}

// swizzled index for element (row, c) in a 128x32 float tile
__device__ __forceinline__ int sw_idx(int row, int c) {
    return (row << 5) + ((((c >> 2) ^ row) & 7) << 2) + (c & 3);
}

#define GEMM_SMEM (2 * 2 * 128 * 32 * 4)   // 65536 bytes

__global__ void __launch_bounds__(256)
tf32gemm_kernel(const float* __restrict__ A,
                const float* __restrict__ W0, const float* __restrict__ W1,
                const float* __restrict__ W2,
                const float* __restrict__ bias,
                float* __restrict__ C0, float* __restrict__ C1,
                float* __restrict__ C2,
                int M, int N, int Kd, int act)
{
    extern __shared__ float smem[];   // [stage][As 4096 | Ws 4096]

    const float* W = (blockIdx.z == 0) ? W0 : (blockIdx.z == 1 ? W1 : W2);
    float*       C = (blockIdx.z == 0) ? C0 : (blockIdx.z == 1 ? C1 : C2);

    const int tid = threadIdx.x;
    const int lane = tid & 31, wrp = tid >> 5;
    const int wm = wrp & 1;          // 0..1
    const int wn = wrp >> 1;         // 0..3
    const int q = lane >> 2, r = lane & 3;
    const int m0 = blockIdx.y * 128;
    const int n0 = blockIdx.x * 128;

    const int lrow = tid >> 3;       // 0..31
    const int lb   = tid & 7;        // float4 block 0..7

    float acc[4][4][4];
#pragma unroll
    for (int i = 0; i < 4; i++)
#pragma unroll
        for (int j = 0; j < 4; j++)
#pragma unroll
            for (int e = 0; e < 4; e++) acc[i][j][e] = 0.f;

    uint32_t sbase = (uint32_t)__cvta_generic_to_shared(smem);

    // issue one stage of cp.async loads
    auto issue = [&](int buf, int k0) {
        uint32_t so = sbase + (uint32_t)buf * 8192u * 4u;
#pragma unroll
        for (int i = 0; i < 4; i++) {
            int row = lrow + i * 32;
            int sidx = (row << 5) + (((lb ^ (row & 7))) << 2);
            cp_async16(so + sidx * 4, A + (size_t)(m0 + row) * Kd + k0 + lb * 4);
            cp_async16(so + (4096 + sidx) * 4, W + (size_t)(n0 + row) * Kd + k0 + lb * 4);
        }
    };

    const int KT = Kd >> 5;
    issue(0, 0);
    cp_commit();

    for (int kt = 0; kt < KT; kt++) {
        const int cur = kt & 1;
        if (kt + 1 < KT) {
            issue(cur ^ 1, (kt + 1) << 5);
            cp_commit();
            cp_wait<1>();
        } else {
            cp_wait<0>();
        }
        __syncthreads();

        const float* As = smem + (size_t)cur * 8192;
        const float* Ws = As + 4096;

#pragma unroll
        for (int kk = 0; kk < 32; kk += 8) {
            uint32_t afr[4][4];
#pragma unroll
            for (int mt = 0; mt < 4; mt++) {
                int mr = wm * 64 + mt * 16 + q;
                afr[mt][0] = f2tf32(As[sw_idx(mr,     kk + r)]);
                afr[mt][1] = f2tf32(As[sw_idx(mr + 8, kk + r)]);
                afr[mt][2] = f2tf32(As[sw_idx(mr,     kk + 4 + r)]);
                afr[mt][3] = f2tf32(As[sw_idx(mr + 8, kk + 4 + r)]);
            }
            uint32_t bfr[4][2];
#pragma unroll
            for (int nt = 0; nt < 4; nt++) {
                int nr = wn * 32 + nt * 8 + q;
                bfr[nt][0] = f2tf32(Ws[sw_idx(nr, kk + r)]);
                bfr[nt][1] = f2tf32(Ws[sw_idx(nr, kk + 4 + r)]);
            }
#pragma unroll
            for (int mt = 0; mt < 4; mt++)
#pragma unroll
                for (int nt = 0; nt < 4; nt++)
                    mma_tf32(acc[mt][nt], afr[mt], bfr[nt]);
        }
        __syncthreads();
    }

    // epilogue
#pragma unroll
    for (int mt = 0; mt < 4; mt++) {
        int row0 = m0 + wm * 64 + mt * 16 + q;
#pragma unroll
        for (int nt = 0; nt < 4; nt++) {
            int col = n0 + wn * 32 + nt * 8 + r * 2;
            float b0 = bias ? bias[col]     : 0.f;
            float b1 = bias ? bias[col + 1] : 0.f;
            float v0 = acc[mt][nt][0] + b0, v1 = acc[mt][nt][1] + b1;
            float v2 = acc[mt][nt][2] + b0, v3 = acc[mt][nt][3] + b1;
            if (act == 1) {
                v0 = fmaxf(v0, 0.f); v1 = fmaxf(v1, 0.f);
                v2 = fmaxf(v2, 0.f); v3 = fmaxf(v3, 0.f);
            }
            *(float2*)(C + (size_t)row0 * N + col)       = make_float2(v0, v1);
            *(float2*)(C + (size_t)(row0 + 8) * N + col) = make_float2(v2, v3);
        }
    }
}

// ---------------- Flash attention with fused-KK trick ------------------------
#define FPAD 66
#define FLASH_SMEM ((4 * 64 * FPAD + 64 + 128) * 4)

__global__ void __launch_bounds__(256)
flash_kernel(const float* __restrict__ q, const float* __restrict__ ke,
             const float* __restrict__ kr, const float* __restrict__ v,
             const float* __restrict__ ub, const float* __restrict__ vb,
             float* __restrict__ out)
{
    extern __shared__ float sm[];
    float* Qt   = sm;                    // [64][66]  Q^T : Qt[d][s]
    float* KKt  = Qt  + 64 * FPAD;       // [64][66]  (ke+kr)^T
    float* Vs   = KKt + 64 * FPAD;       // [64][66]  V[t][d]
    float* St   = Vs  + 64 * FPAD;       // [64][66]  P^T
    float* biasT = St + 64 * FPAD;       // [64]
    float* ubs  = biasT + 64;            // [64]
    float* vbs  = ubs + 64;              // [64]

    const int qb = blockIdx.x, h = blockIdx.y, b = blockIdx.z;
    const int tid = threadIdx.x;
    const int tx = tid & 15, ty = tid >> 4;
    const int lane = tid & 31, wrp = tid >> 5;

    if (tid < 64)       ubs[tid]      = ub[h * 64 + tid];
    else if (tid < 128) vbs[tid - 64] = vb[h * 64 + (tid - 64)];

#pragma unroll
    for (int it = 0; it < 4; it++) {
        int idx = tid + it * 256;
        int s = idx >> 4, d4 = (idx & 15) * 4;
        float4 qv = *(const float4*)(q + ((size_t)((qb * 64 + s) * BATCH + b)) * DMODEL + h * 64 + d4);
        Qt[(d4 + 0) * FPAD + s] = qv.x;
        Qt[(d4 + 1) * FPAD + s] = qv.y;
        Qt[(d4 + 2) * FPAD + s] = qv.z;
        Qt[(d4 + 3) * FPAD + s] = qv.w;
    }

    float m_i[4], l_i[4], O[4][4];
#pragma unroll
    for (int i = 0; i < 4; i++) {
        m_i[i] = -1e30f; l_i[i] = 0.f;
#pragma unroll
        for (int j = 0; j < 4; j++) O[i][j] = 0.f;
    }

    const int ntiles = 17 + qb;
    for (int tt = 0; tt < ntiles; tt++) {
        const int t0 = tt * 64;

#pragma unroll
        for (int rr = 0; rr < 8; rr++) {
            int t = wrp * 8 + rr;
            size_t base = ((size_t)((t0 + t) * BATCH + b)) * DMODEL + h * 64;
            float2 kev = *(const float2*)(ke + base + lane * 2);
            float2 krv = *(const float2*)(kr + base + lane * 2);
            KKt[(lane * 2 + 0) * FPAD + t] = kev.x + krv.x;
            KKt[(lane * 2 + 1) * FPAD + t] = kev.y + krv.y;
            float bsum = ubs[lane * 2] * kev.x + ubs[lane * 2 + 1] * kev.y
                       + vbs[lane * 2] * krv.x + vbs[lane * 2 + 1] * krv.y;
#pragma unroll
            for (int off = 16; off; off >>= 1)
                bsum += __shfl_xor_sync(0xffffffffu, bsum, off);
            if (lane == 0) biasT[t] = bsum;
        }
#pragma unroll
        for (int it = 0; it < 4; it++) {
            int idx = tid + it * 256;
            int t = idx >> 4, d4 = (idx & 15) * 4;
            float4 vv = *(const float4*)(v + ((size_t)((t0 + t) * BATCH + b)) * DMODEL + h * 64 + d4);
            Vs[t * FPAD + d4 + 0] = vv.x;
            Vs[t * FPAD + d4 + 1] = vv.y;
            Vs[t * FPAD + d4 + 2] = vv.z;
            Vs[t * FPAD + d4 + 3] = vv.w;
        }
        __syncthreads();

        float sc[4][4];
#pragma unroll
        for (int i = 0; i < 4; i++)
#pragma unroll
            for (int j = 0; j < 4; j++) sc[i][j] = 0.f;

#pragma unroll 8
        for (int d = 0; d < 64; d++) {
            float a[4], bb[4];
            float2 qa = *(const float2*)&Qt[d * FPAD + ty * 4];
            float2 qc = *(const float2*)&Qt[d * FPAD + ty * 4 + 2];
            float2 ka = *(const float2*)&KKt[d * FPAD + tx * 4];
            float2 kc = *(const float2*)&KKt[d * FPAD + tx * 4 + 2];
            a[0] = qa.x; a[1] = qa.y; a[2] = qc.x; a[3] = qc.y;
            bb[0] = ka.x; bb[1] = ka.y; bb[2] = kc.x; bb[3] = kc.y;
#pragma unroll
            for (int i = 0; i < 4; i++)
#pragma unroll
                for (int j = 0; j < 4; j++)
                    sc[i][j] = fmaf(a[i], bb[j], sc[i][j]);
        }

        const bool diag = (tt == 16 + qb);
#pragma unroll
        for (int j = 0; j < 4; j++) {
            float bj = biasT[tx * 4 + j];
#pragma unroll
            for (int i = 0; i < 4; i++) {
                float vv = (sc[i][j] + bj) * 0.125f;
                if (diag && (tx * 4 + j) > (ty * 4 + i)) vv = -1e30f;
                sc[i][j] = vv;
            }
        }

#pragma unroll
        for (int i = 0; i < 4; i++) {
            float mt = fmaxf(fmaxf(sc[i][0], sc[i][1]), fmaxf(sc[i][2], sc[i][3]));
#pragma unroll
            for (int off = 8; off; off >>= 1)
                mt = fmaxf(mt, __shfl_xor_sync(0xffffffffu, mt, off, 16));
            float mnew = fmaxf(m_i[i], mt);
            float c = __expf(m_i[i] - mnew);
            l_i[i] *= c;
#pragma unroll
            for (int j = 0; j < 4; j++) O[i][j] *= c;
            float ps = 0.f;
#pragma unroll
            for (int j = 0; j < 4; j++) {
                float pv = __expf(sc[i][j] - mnew);
                sc[i][j] = pv;
                ps += pv;
            }
            l_i[i] += ps;
            m_i[i] = mnew;
        }
#pragma unroll
        for (int i = 0; i < 4; i++)
#pragma unroll
            for (int j = 0; j < 4; j++)
                St[(tx * 4 + j) * FPAD + ty * 4 + i] = sc[i][j];
        __syncthreads();

#pragma unroll 8
        for (int t = 0; t < 64; t++) {
            float a[4], bb[4];
            float2 pa = *(const float2*)&St[t * FPAD + ty * 4];
            float2 pc = *(const float2*)&St[t * FPAD + ty * 4 + 2];
            float2 va = *(const float2*)&Vs[t * FPAD + tx * 4];
            float2 vc = *(const float2*)&Vs[t * FPAD + tx * 4 + 2];
            a[0] = pa.x; a[1] = pa.y; a[2] = pc.x; a[3] = pc.y;
            bb[0] = va.x; bb[1] = va.y; bb[2] = vc.x; bb[3] = vc.y;
#pragma unroll
            for (int i = 0; i < 4; i++)
#pragma unroll
                for (int j = 0; j < 4; j++)
                    O[i][j] = fmaf(a[i], bb[j], O[i][j]);
        }
        __syncthreads();
    }

#pragma unroll
    for (int i = 0; i < 4; i++) {
        float lt = l_i[i];
#pragma unroll
        for (int off = 8; off; off >>= 1)
            lt += __shfl_xor_sync(0xffffffffu, lt, off, 16);
        float inv = 1.f / lt;
        int s = qb * 64 + ty * 4 + i;
        float* orow = out + ((size_t)(s * BATCH + b)) * DMODEL + h * 64 + tx * 4;
#pragma unroll
        for (int j = 0; j < 4; j++) orow[j] = O[i][j] * inv;
    }
}

// ---------------- LayerNorm(a + res) * g + b --------------------------------
__global__ void __launch_bounds__(256)
ln_kernel(const float* __restrict__ a, const float* __restrict__ res,
          const float* __restrict__ g, const float* __restrict__ bta,
          float* __restrict__ out)
{
    const int row = blockIdx.x;
    const int tid = threadIdx.x;
    const int lane = tid & 31, wrp = tid >> 5;
    __shared__ float red[8];
    __shared__ float bc;

    float vals[4];
    float s = 0.f;
    const float* ar = a + (size_t)row * DMODEL;
    const float* rr = res + (size_t)row * DMODEL;
#pragma unroll
    for (int i = 0; i < 4; i++) {
        int d = tid + i * 256;
        vals[i] = ar[d] + rr[d];
        s += vals[i];
    }
#pragma unroll
    for (int off = 16; off; off >>= 1) s += __shfl_xor_sync(0xffffffffu, s, off);
    if (lane == 0) red[wrp] = s;
    __syncthreads();
    if (tid == 0) {
        float t = 0.f;
#pragma unroll
        for (int w = 0; w < 8; w++) t += red[w];
        bc = t * (1.f / DMODEL);
    }
    __syncthreads();
    const float mu = bc;

    float vs = 0.f;
#pragma unroll
    for (int i = 0; i < 4; i++) {
        float dd = vals[i] - mu;
        vs += dd * dd;
    }
#pragma unroll
    for (int off = 16; off; off >>= 1) vs += __shfl_xor_sync(0xffffffffu, vs, off);
    __syncthreads();
    if (lane == 0) red[wrp] = vs;
    __syncthreads();
    if (tid == 0) {
        float t = 0.f;
#pragma unroll
        for (int w = 0; w < 8; w++) t += red[w];
        bc = rsqrtf(t * (1.f / DMODEL) + 1e-5f);
    }
    __syncthreads();
    const float rstd = bc;

    float* orow = out + (size_t)row * DMODEL;
#pragma unroll
    for (int i = 0; i < 4; i++) {
        int d = tid + i * 256;
        orow[d] = (vals[i] - mu) * rstd * g[d] + bta[d];
    }
}

// ---------------- launcher ---------------------------------------------------
extern "C" void kernel_launch(void* const* d_in, const int* in_sizes, int n_in,
                              void* d_out, int out_size)
{
    const float* x      = (const float*)d_in[0];
    const float* p      = (const float*)d_in[1];
    /* mask d_in[2] is analytic: unused */
    const float* memory = (const float*)d_in[3];
    const float* u_bias = (const float*)d_in[4];
    const float* v_bias = (const float*)d_in[5];
    const float* wq  = (const float*)d_in[6];
    const float* wke = (const float*)d_in[7];
    const float* wkr = (const float*)d_in[8];
    const float* wv  = (const float*)d_in[9];
    const float* wc  = (const float*)d_in[10];
    const float* w1  = (const float*)d_in[11];
    const float* w1b = (const float*)d_in[12];
    const float* w2  = (const float*)d_in[13];
    const float* w2b = (const float*)d_in[14];
    const float* ln1g = (const float*)d_in[15];
    const float* ln1b = (const float*)d_in[16];
    const float* ln2g = (const float*)d_in[17];
    const float* ln2b = (const float*)d_in[18];
    float* out = (float*)d_out;

    float *q, *ke, *kr, *v, *av, *tbuf, *ubuf, *h1;
    cudaGetSymbolAddress((void**)&q,    g_q);
    cudaGetSymbolAddress((void**)&ke,   g_ke);
    cudaGetSymbolAddress((void**)&kr,   g_kr);
    cudaGetSymbolAddress((void**)&v,    g_v);
    cudaGetSymbolAddress((void**)&av,   g_av);
    cudaGetSymbolAddress((void**)&tbuf, g_t);
    cudaGetSymbolAddress((void**)&ubuf, g_u);
    cudaGetSymbolAddress((void**)&h1,   g_h1);

    cudaFuncSetAttribute(tf32gemm_kernel,
                         cudaFuncAttributeMaxDynamicSharedMemorySize, GEMM_SMEM);
    cudaFuncSetAttribute(flash_kernel,
                         cudaFuncAttributeMaxDynamicSharedMemorySize, FLASH_SMEM);

    const dim3 blk(256);
    const size_t half = (size_t)ROWS_X * DMODEL;

    // batched projections from x: q, ke (second half), v (second half)
    tf32gemm_kernel<<<dim3(8, 16, 3), blk, GEMM_SMEM>>>(
        x, wq, wke, wv, nullptr, q, ke + half, v + half,
        ROWS_X, DMODEL, DMODEL, 0);
    // batched projections from memory: ke (first half), v (first half)
    tf32gemm_kernel<<<dim3(8, 16, 2), blk, GEMM_SMEM>>>(
        memory, wke, wv, nullptr, nullptr, ke, v, nullptr,
        ROWS_X, DMODEL, DMODEL, 0);
    // relative-position keys from p
    tf32gemm_kernel<<<dim3(8, 32, 1), blk, GEMM_SMEM>>>(
        p, wkr, nullptr, nullptr, nullptr, kr, nullptr, nullptr,
        ROWS_T, DMODEL, DMODEL, 0);

    // attention
    flash_kernel<<<dim3(16, HEADS, BATCH), blk, FLASH_SMEM>>>(q, ke, kr, v, u_bias, v_bias, av);

    // output proj + LN1
    tf32gemm_kernel<<<dim3(8, 16, 1), blk, GEMM_SMEM>>>(
        av, wc, nullptr, nullptr, nullptr, tbuf, nullptr, nullptr,
        ROWS_X, DMODEL, DMODEL, 0);
    ln_kernel<<<ROWS_X, blk>>>(tbuf, x, ln1g, ln1b, ubuf);

    // FFN + LN2
    tf32gemm_kernel<<<dim3(32, 16, 1), blk, GEMM_SMEM>>>(
        ubuf, w1, nullptr, nullptr, w1b, h1, nullptr, nullptr,
        ROWS_X, FFDIM, DMODEL, 1);
    tf32gemm_kernel<<<dim3(8, 16, 1), blk, GEMM_SMEM>>>(
        h1, w2, nullptr, nullptr, w2b, tbuf, nullptr, nullptr,
        ROWS_X, DMODEL, FFDIM, 0);
    ln_kernel<<<ROWS_X, blk>>>(tbuf, ubuf, ln2g, ln2b, out);
}

// round 4
// speedup vs baseline: 1.5638x; 1.5638x over previous
#include <cuda_runtime.h>
#include <cuda_bf16.h>
#include <math.h>
#include <stdint.h>

// Problem constants
#define S_LEN 1024
#define BATCH 2
#define DMODEL 1024
#define HEADS 16
#define HDIM 64
#define TLEN 2048
#define FFDIM 4096
#define ROWS_X (S_LEN * BATCH)     // 2048
#define ROWS_T (TLEN * BATCH)      // 4096

// ---------------- scratch buffers (device globals) ---------------------------
__device__ float g_q [ROWS_X * DMODEL];
__device__ float g_ke[ROWS_T * DMODEL];
__device__ float g_kr[ROWS_T * DMODEL];
__device__ float g_v [ROWS_T * DMODEL];
__device__ float g_av[ROWS_X * DMODEL];
__device__ float g_t [ROWS_X * DMODEL];
__device__ float g_u [ROWS_X * DMODEL];
__device__ float g_h1[ROWS_X * FFDIM];
// flash-prep outputs: per (b,h) contiguous, tf32-rounded bit patterns
__device__ uint32_t g_kk2 [BATCH * HEADS * TLEN * HDIM];
__device__ uint32_t g_v2  [BATCH * HEADS * TLEN * HDIM];
__device__ float    g_bias[BATCH * HEADS * TLEN];

// ---------------- common PTX helpers ----------------------------------------
__device__ __forceinline__ uint32_t f2tf32(float f) {
    uint32_t r;
    asm("cvt.rna.tf32.f32 %0, %1;" : "=r"(r) : "f"(f));
    return r;
}
__device__ __forceinline__ void cp_async16(uint32_t saddr, const void* gptr) {
    asm volatile("cp.async.cg.shared.global [%0], [%1], 16;\n"
                 :: "r"(saddr), "l"(gptr));
}
__device__ __forceinline__ void cp_commit() {
    asm volatile("cp.async.commit_group;\n");
}
template <int N>
__device__ __forceinline__ void cp_wait() {
    asm volatile("cp.async.wait_group %0;\n" :: "n"(N));
}
__device__ __forceinline__ void mma_tf32(float* d, const uint32_t* a, const uint32_t* b) {
    asm volatile(
        "mma.sync.aligned.m16n8k8.row.col.f32.tf32.tf32.f32 "
        "{%0,%1,%2,%3}, {%4,%5,%6,%7}, {%8,%9}, {%0,%1,%2,%3};\n"
        : "+f"(d[0]), "+f"(d[1]), "+f"(d[2]), "+f"(d[3])
        : "r"(a[0]), "r"(a[1]), "r"(a[2]), "r"(a[3]), "r"(b[0]), "r"(b[1]));
}

// ---------------- tf32 tensor-core GEMM (unchanged from R3) -----------------
__device__ __forceinline__ int sw_idx(int row, int c) {
    return (row << 5) + ((((c >> 2) ^ row) & 7) << 2) + (c & 3);
}

#define GEMM_SMEM (2 * 2 * 128 * 32 * 4)   // 65536 bytes

__global__ void __launch_bounds__(256)
tf32gemm_kernel(const float* __restrict__ A,
                const float* __restrict__ W0, const float* __restrict__ W1,
                const float* __restrict__ W2,
                const float* __restrict__ bias,
                float* __restrict__ C0, float* __restrict__ C1,
                float* __restrict__ C2,
                int M, int N, int Kd, int act)
{
    extern __shared__ float smem[];

    const float* W = (blockIdx.z == 0) ? W0 : (blockIdx.z == 1 ? W1 : W2);
    float*       C = (blockIdx.z == 0) ? C0 : (blockIdx.z == 1 ? C1 : C2);

    const int tid = threadIdx.x;
    const int lane = tid & 31, wrp = tid >> 5;
    const int wm = wrp & 1;
    const int wn = wrp >> 1;
    const int q = lane >> 2, r = lane & 3;
    const int m0 = blockIdx.y * 128;
    const int n0 = blockIdx.x * 128;

    const int lrow = tid >> 3;
    const int lb   = tid & 7;

    float acc[4][4][4];
#pragma unroll
    for (int i = 0; i < 4; i++)
#pragma unroll
        for (int j = 0; j < 4; j++)
#pragma unroll
            for (int e = 0; e < 4; e++) acc[i][j][e] = 0.f;

    uint32_t sbase = (uint32_t)__cvta_generic_to_shared(smem);

    auto issue = [&](int buf, int k0) {
        uint32_t so = sbase + (uint32_t)buf * 8192u * 4u;
#pragma unroll
        for (int i = 0; i < 4; i++) {
            int row = lrow + i * 32;
            int sidx = (row << 5) + (((lb ^ (row & 7))) << 2);
            cp_async16(so + sidx * 4, A + (size_t)(m0 + row) * Kd + k0 + lb * 4);
            cp_async16(so + (4096 + sidx) * 4, W + (size_t)(n0 + row) * Kd + k0 + lb * 4);
        }
    };

    const int KT = Kd >> 5;
    issue(0, 0);
    cp_commit();

    for (int kt = 0; kt < KT; kt++) {
        const int cur = kt & 1;
        if (kt + 1 < KT) {
            issue(cur ^ 1, (kt + 1) << 5);
            cp_commit();
            cp_wait<1>();
        } else {
            cp_wait<0>();
        }
        __syncthreads();

        const float* As = smem + (size_t)cur * 8192;
        const float* Ws = As + 4096;

#pragma unroll
        for (int kk = 0; kk < 32; kk += 8) {
            uint32_t afr[4][4];
#pragma unroll
            for (int mt = 0; mt < 4; mt++) {
                int mr = wm * 64 + mt * 16 + q;
                afr[mt][0] = f2tf32(As[sw_idx(mr,     kk + r)]);
                afr[mt][1] = f2tf32(As[sw_idx(mr + 8, kk + r)]);
                afr[mt][2] = f2tf32(As[sw_idx(mr,     kk + 4 + r)]);
                afr[mt][3] = f2tf32(As[sw_idx(mr + 8, kk + 4 + r)]);
            }
            uint32_t bfr[4][2];
#pragma unroll
            for (int nt = 0; nt < 4; nt++) {
                int nr = wn * 32 + nt * 8 + q;
                bfr[nt][0] = f2tf32(Ws[sw_idx(nr, kk + r)]);
                bfr[nt][1] = f2tf32(Ws[sw_idx(nr, kk + 4 + r)]);
            }
#pragma unroll
            for (int mt = 0; mt < 4; mt++)
#pragma unroll
                for (int nt = 0; nt < 4; nt++)
                    mma_tf32(acc[mt][nt], afr[mt], bfr[nt]);
        }
        __syncthreads();
    }

#pragma unroll
    for (int mt = 0; mt < 4; mt++) {
        int row0 = m0 + wm * 64 + mt * 16 + q;
#pragma unroll
        for (int nt = 0; nt < 4; nt++) {
            int col = n0 + wn * 32 + nt * 8 + r * 2;
            float b0 = bias ? bias[col]     : 0.f;
            float b1 = bias ? bias[col + 1] : 0.f;
            float v0 = acc[mt][nt][0] + b0, v1 = acc[mt][nt][1] + b1;
            float v2 = acc[mt][nt][2] + b0, v3 = acc[mt][nt][3] + b1;
            if (act == 1) {
                v0 = fmaxf(v0, 0.f); v1 = fmaxf(v1, 0.f);
                v2 = fmaxf(v2, 0.f); v3 = fmaxf(v3, 0.f);
            }
            *(float2*)(C + (size_t)row0 * N + col)       = make_float2(v0, v1);
            *(float2*)(C + (size_t)(row0 + 8) * N + col) = make_float2(v2, v3);
        }
    }
}

// ---------------- prep: KK = ke+kr (tf32), bias = u.ke + v.kr, repack V -----
__global__ void __launch_bounds__(256)
prep_kernel(const float* __restrict__ ke, const float* __restrict__ kr,
            const float* __restrict__ v,
            const float* __restrict__ ub, const float* __restrict__ vb,
            uint32_t* __restrict__ kk2, uint32_t* __restrict__ v2,
            float* __restrict__ biasO)
{
    const int row = blockIdx.x;          // = t*BATCH + b
    const int t = row / BATCH, b = row % BATCH;
    const int tid = threadIdx.x;
    const int h = tid >> 4, l16 = tid & 15, d0 = l16 * 4;

    const size_t src = (size_t)row * DMODEL + h * HDIM + d0;
    float4 kev = *(const float4*)(ke + src);
    float4 krv = *(const float4*)(kr + src);
    float4 vv  = *(const float4*)(v  + src);

    const size_t dst = ((size_t)(b * HEADS + h) * TLEN + t) * HDIM + d0;
    uint4 kko, vvo;
    kko.x = f2tf32(kev.x + krv.x); kko.y = f2tf32(kev.y + krv.y);
    kko.z = f2tf32(kev.z + krv.z); kko.w = f2tf32(kev.w + krv.w);
    vvo.x = f2tf32(vv.x); vvo.y = f2tf32(vv.y);
    vvo.z = f2tf32(vv.z); vvo.w = f2tf32(vv.w);
    *(uint4*)(kk2 + dst) = kko;
    *(uint4*)(v2  + dst) = vvo;

    float4 u4 = *(const float4*)(ub + h * HDIM + d0);
    float4 w4 = *(const float4*)(vb + h * HDIM + d0);
    float bsum = u4.x * kev.x + u4.y * kev.y + u4.z * kev.z + u4.w * kev.w
               + w4.x * krv.x + w4.y * krv.y + w4.z * krv.z + w4.w * krv.w;
#pragma unroll
    for (int off = 8; off; off >>= 1)
        bsum += __shfl_xor_sync(0xffffffffu, bsum, off, 16);
    if (l16 == 0) biasO[(size_t)(b * HEADS + h) * TLEN + t] = bsum;
}

// ---------------- tensor-core flash attention --------------------------------
#define FQS  0
#define FPS  8192
#define FKK  16384
#define FVS  20480
#define FBI  24576
#define FLASH_SMEM ((24576 + 64) * 4)

__device__ __forceinline__ int sw64(int row, int c) {
    return (row << 6) + (((c >> 2) ^ (row & 7)) << 2) + (c & 3);
}

__global__ void __launch_bounds__(256, 2)
flash_tc_kernel(const float* __restrict__ qg,
                const uint32_t* __restrict__ kk2,
                const uint32_t* __restrict__ v2,
                const float* __restrict__ biasG,
                float* __restrict__ out)
{
    extern __shared__ uint32_t fsm[];
    uint32_t* Qs  = fsm + FQS;
    uint32_t* Ps  = fsm + FPS;
    uint32_t* KKs = fsm + FKK;
    uint32_t* Vs  = fsm + FVS;
    float*    biasS = (float*)(fsm + FBI);

    const int qb = blockIdx.x, h = blockIdx.y, b = blockIdx.z;
    const int tid = threadIdx.x;
    const int lane = tid & 31, wid = tid >> 5;
    const int q = lane >> 2, r = lane & 3;
    const int mw = wid * 16;

    const uint32_t sbase = (uint32_t)__cvta_generic_to_shared(fsm);
    const size_t   bh    = (size_t)(b * HEADS + h) * TLEN;
    const uint32_t* kkbh = kk2 + bh * HDIM;
    const uint32_t* vbh  = v2  + bh * HDIM;
    const float*    bibh = biasG + bh;

    // ---- load Q tile (once): tf32-round in registers, store swizzled -------
#pragma unroll
    for (int it = 0; it < 8; it++) {
        int idx = tid + it * 256;
        int row = idx >> 4, g4 = (idx & 15) * 4;
        const float4 qv = *(const float4*)(qg +
            ((size_t)((qb * 128 + row) * BATCH + b)) * DMODEL + h * HDIM + g4);
        uint4 qo;
        qo.x = f2tf32(qv.x); qo.y = f2tf32(qv.y);
        qo.z = f2tf32(qv.z); qo.w = f2tf32(qv.w);
        *(uint4*)(Qs + sw64(row, g4)) = qo;
    }

    auto issueKV = [&](int t0) {
#pragma unroll
        for (int it = 0; it < 4; it++) {
            int idx = tid + it * 256;
            int row = idx >> 4, g4 = (idx & 15) * 4;
            size_t src = (size_t)(t0 + row) * HDIM + g4;
            uint32_t sdst = sbase + (uint32_t)sw64(row, g4) * 4;
            cp_async16(sdst + FKK * 4, kkbh + src);
            cp_async16(sdst + FVS * 4, vbh + src);
        }
        if (tid < 16)
            cp_async16(sbase + FBI * 4 + tid * 16, bibh + t0 + tid * 4);
    };

    issueKV(0);
    cp_commit();
    cp_wait<0>();
    __syncthreads();

    float m0 = -1e30f, m1 = -1e30f, l0 = 0.f, l1 = 0.f;
    float O[8][4];
#pragma unroll
    for (int nt = 0; nt < 8; nt++)
#pragma unroll
        for (int e = 0; e < 4; e++) O[nt][e] = 0.f;

    const int ntiles = 18 + 2 * qb;
    const int srow0 = qb * 128 + mw + q;

    for (int tt = 0; tt < ntiles; tt++) {
        const int t0 = tt * 64;

        // ---- scores: S = Q @ KK^T ------------------------------------------
        float sc[8][4];
#pragma unroll
        for (int nt = 0; nt < 8; nt++)
#pragma unroll
            for (int e = 0; e < 4; e++) sc[nt][e] = 0.f;

#pragma unroll
        for (int kk = 0; kk < 64; kk += 8) {
            uint32_t a[4];
            a[0] = Qs[sw64(mw + q,     kk + r)];
            a[1] = Qs[sw64(mw + q + 8, kk + r)];
            a[2] = Qs[sw64(mw + q,     kk + r + 4)];
            a[3] = Qs[sw64(mw + q + 8, kk + r + 4)];
#pragma unroll
            for (int nt = 0; nt < 8; nt++) {
                uint32_t bb[2];
                bb[0] = KKs[sw64(nt * 8 + q, kk + r)];
                bb[1] = KKs[sw64(nt * 8 + q, kk + r + 4)];
                mma_tf32(sc[nt], a, bb);
            }
        }

        // ---- bias + scale + causal mask ------------------------------------
        const bool mt_ = (tt >= 16 + 2 * qb);
        float tmax0 = -1e30f, tmax1 = -1e30f;
#pragma unroll
        for (int nt = 0; nt < 8; nt++) {
            const int colb = nt * 8 + 2 * r;
            const float bi0 = biasS[colb], bi1 = biasS[colb + 1];
            float v0 = (sc[nt][0] + bi0) * 0.125f;
            float v1 = (sc[nt][1] + bi1) * 0.125f;
            float v2 = (sc[nt][2] + bi0) * 0.125f;
            float v3 = (sc[nt][3] + bi1) * 0.125f;
            if (mt_) {
                const int tc = t0 + colb;
                if (tc     > S_LEN + srow0)     v0 = -1e30f;
                if (tc + 1 > S_LEN + srow0)     v1 = -1e30f;
                if (tc     > S_LEN + srow0 + 8) v2 = -1e30f;
                if (tc + 1 > S_LEN + srow0 + 8) v3 = -1e30f;
            }
            sc[nt][0] = v0; sc[nt][1] = v1; sc[nt][2] = v2; sc[nt][3] = v3;
            tmax0 = fmaxf(tmax0, fmaxf(v0, v1));
            tmax1 = fmaxf(tmax1, fmaxf(v2, v3));
        }
        tmax0 = fmaxf(tmax0, __shfl_xor_sync(0xffffffffu, tmax0, 1));
        tmax0 = fmaxf(tmax0, __shfl_xor_sync(0xffffffffu, tmax0, 2));
        tmax1 = fmaxf(tmax1, __shfl_xor_sync(0xffffffffu, tmax1, 1));
        tmax1 = fmaxf(tmax1, __shfl_xor_sync(0xffffffffu, tmax1, 2));

        const float mnew0 = fmaxf(m0, tmax0);
        const float mnew1 = fmaxf(m1, tmax1);
        const float c0 = __expf(m0 - mnew0);
        const float c1 = __expf(m1 - mnew1);
        m0 = mnew0; m1 = mnew1;
        l0 *= c0; l1 *= c1;

        float ps0 = 0.f, ps1 = 0.f;
#pragma unroll
        for (int nt = 0; nt < 8; nt++) {
            float p0 = __expf(sc[nt][0] - mnew0);
            float p1 = __expf(sc[nt][1] - mnew0);
            float p2 = __expf(sc[nt][2] - mnew1);
            float p3 = __expf(sc[nt][3] - mnew1);
            ps0 += p0 + p1; ps1 += p2 + p3;
            O[nt][0] *= c0; O[nt][1] *= c0;
            O[nt][2] *= c1; O[nt][3] *= c1;
            uint2 s0, s1;
            s0.x = f2tf32(p0); s0.y = f2tf32(p1);
            s1.x = f2tf32(p2); s1.y = f2tf32(p3);
            *(uint2*)&Ps[sw64(mw + q,     nt * 8 + 2 * r)] = s0;
            *(uint2*)&Ps[sw64(mw + q + 8, nt * 8 + 2 * r)] = s1;
        }
        l0 += ps0; l1 += ps1;
        __syncwarp();

        // ---- O += P @ V -----------------------------------------------------
#pragma unroll
        for (int kk = 0; kk < 64; kk += 8) {
            uint32_t a[4];
            a[0] = Ps[sw64(mw + q,     kk + r)];
            a[1] = Ps[sw64(mw + q + 8, kk + r)];
            a[2] = Ps[sw64(mw + q,     kk + r + 4)];
            a[3] = Ps[sw64(mw + q + 8, kk + r + 4)];
#pragma unroll
            for (int nt = 0; nt < 8; nt++) {
                uint32_t bb[2];
                bb[0] = Vs[sw64(kk + r,     nt * 8 + q)];
                bb[1] = Vs[sw64(kk + r + 4, nt * 8 + q)];
                mma_tf32(O[nt], a, bb);
            }
        }
        __syncthreads();

        if (tt + 1 < ntiles) {
            issueKV(t0 + 64);
            cp_commit();
            cp_wait<0>();
            __syncthreads();
        }
    }

    // ---- finalize ----------------------------------------------------------
    l0 += __shfl_xor_sync(0xffffffffu, l0, 1);
    l0 += __shfl_xor_sync(0xffffffffu, l0, 2);
    l1 += __shfl_xor_sync(0xffffffffu, l1, 1);
    l1 += __shfl_xor_sync(0xffffffffu, l1, 2);
    const float inv0 = 1.f / l0, inv1 = 1.f / l1;

#pragma unroll
    for (int nt = 0; nt < 8; nt++) {
        const int col = nt * 8 + 2 * r;
        const int row0 = qb * 128 + mw + q;
        *(float2*)(out + ((size_t)(row0 * BATCH + b)) * DMODEL + h * HDIM + col)
            = make_float2(O[nt][0] * inv0, O[nt][1] * inv0);
        *(float2*)(out + ((size_t)((row0 + 8) * BATCH + b)) * DMODEL + h * HDIM + col)
            = make_float2(O[nt][2] * inv1, O[nt][3] * inv1);
    }
}

// ---------------- LayerNorm(a + res) * g + b --------------------------------
__global__ void __launch_bounds__(256)
ln_kernel(const float* __restrict__ a, const float* __restrict__ res,
          const float* __restrict__ g, const float* __restrict__ bta,
          float* __restrict__ out)
{
    const int row = blockIdx.x;
    const int tid = threadIdx.x;
    const int lane = tid & 31, wrp = tid >> 5;
    __shared__ float red[8];
    __shared__ float bc;

    float vals[4];
    float s = 0.f;
    const float* ar = a + (size_t)row * DMODEL;
    const float* rr = res + (size_t)row * DMODEL;
#pragma unroll
    for (int i = 0; i < 4; i++) {
        int d = tid + i * 256;
        vals[i] = ar[d] + rr[d];
        s += vals[i];
    }
#pragma unroll
    for (int off = 16; off; off >>= 1) s += __shfl_xor_sync(0xffffffffu, s, off);
    if (lane == 0) red[wrp] = s;
    __syncthreads();
    if (tid == 0) {
        float t = 0.f;
#pragma unroll
        for (int w = 0; w < 8; w++) t += red[w];
        bc = t * (1.f / DMODEL);
    }
    __syncthreads();
    const float mu = bc;

    float vs = 0.f;
#pragma unroll
    for (int i = 0; i < 4; i++) {
        float dd = vals[i] - mu;
        vs += dd * dd;
    }
#pragma unroll
    for (int off = 16; off; off >>= 1) vs += __shfl_xor_sync(0xffffffffu, vs, off);
    __syncthreads();
    if (lane == 0) red[wrp] = vs;
    __syncthreads();
    if (tid == 0) {
        float t = 0.f;
#pragma unroll
        for (int w = 0; w < 8; w++) t += red[w];
        bc = rsqrtf(t * (1.f / DMODEL) + 1e-5f);
    }
    __syncthreads();
    const float rstd = bc;

    float* orow = out + (size_t)row * DMODEL;
#pragma unroll
    for (int i = 0; i < 4; i++) {
        int d = tid + i * 256;
        orow[d] = (vals[i] - mu) * rstd * g[d] + bta[d];
    }
}

// ---------------- launcher ---------------------------------------------------
extern "C" void kernel_launch(void* const* d_in, const int* in_sizes, int n_in,
                              void* d_out, int out_size)
{
    const float* x      = (const float*)d_in[0];
    const float* p      = (const float*)d_in[1];
    /* mask d_in[2] is analytic: unused */
    const float* memory = (const float*)d_in[3];
    const float* u_bias = (const float*)d_in[4];
    const float* v_bias = (const float*)d_in[5];
    const float* wq  = (const float*)d_in[6];
    const float* wke = (const float*)d_in[7];
    const float* wkr = (const float*)d_in[8];
    const float* wv  = (const float*)d_in[9];
    const float* wc  = (const float*)d_in[10];
    const float* w1  = (const float*)d_in[11];
    const float* w1b = (const float*)d_in[12];
    const float* w2  = (const float*)d_in[13];
    const float* w2b = (const float*)d_in[14];
    const float* ln1g = (const float*)d_in[15];
    const float* ln1b = (const float*)d_in[16];
    const float* ln2g = (const float*)d_in[17];
    const float* ln2b = (const float*)d_in[18];
    float* out = (float*)d_out;

    float *q, *ke, *kr, *v, *av, *tbuf, *ubuf, *h1, *bias2;
    uint32_t *kk2, *v2;
    cudaGetSymbolAddress((void**)&q,    g_q);
    cudaGetSymbolAddress((void**)&ke,   g_ke);
    cudaGetSymbolAddress((void**)&kr,   g_kr);
    cudaGetSymbolAddress((void**)&v,    g_v);
    cudaGetSymbolAddress((void**)&av,   g_av);
    cudaGetSymbolAddress((void**)&tbuf, g_t);
    cudaGetSymbolAddress((void**)&ubuf, g_u);
    cudaGetSymbolAddress((void**)&h1,   g_h1);
    cudaGetSymbolAddress((void**)&kk2,  g_kk2);
    cudaGetSymbolAddress((void**)&v2,   g_v2);
    cudaGetSymbolAddress((void**)&bias2, g_bias);

    cudaFuncSetAttribute(tf32gemm_kernel,
                         cudaFuncAttributeMaxDynamicSharedMemorySize, GEMM_SMEM);
    cudaFuncSetAttribute(flash_tc_kernel,
                         cudaFuncAttributeMaxDynamicSharedMemorySize, FLASH_SMEM);

    const dim3 blk(256);
    const size_t half = (size_t)ROWS_X * DMODEL;

    // batched projections from x: q, ke (second half), v (second half)
    tf32gemm_kernel<<<dim3(8, 16, 3), blk, GEMM_SMEM>>>(
        x, wq, wke, wv, nullptr, q, ke + half, v + half,
        ROWS_X, DMODEL, DMODEL, 0);
    // batched projections from memory: ke (first half), v (first half)
    tf32gemm_kernel<<<dim3(8, 16, 2), blk, GEMM_SMEM>>>(
        memory, wke, wv, nullptr, nullptr, ke, v, nullptr,
        ROWS_X, DMODEL, DMODEL, 0);
    // relative-position keys from p
    tf32gemm_kernel<<<dim3(8, 32, 1), blk, GEMM_SMEM>>>(
        p, wkr, nullptr, nullptr, nullptr, kr, nullptr, nullptr,
        ROWS_T, DMODEL, DMODEL, 0);

    // prep: fuse KK, bias, repack V (tf32 bits, per-(b,h) contiguous)
    prep_kernel<<<ROWS_T, blk>>>(ke, kr, v, u_bias, v_bias, kk2, v2, bias2);

    // tensor-core flash attention
    flash_tc_kernel<<<dim3(8, HEADS, BATCH), blk, FLASH_SMEM>>>(
        q, kk2, v2, bias2, av);

    // output proj + LN1
    tf32gemm_kernel<<<dim3(8, 16, 1), blk, GEMM_SMEM>>>(
        av, wc, nullptr, nullptr, nullptr, tbuf, nullptr, nullptr,
        ROWS_X, DMODEL, DMODEL, 0);
    ln_kernel<<<ROWS_X, blk>>>(tbuf, x, ln1g, ln1b, ubuf);

    // FFN + LN2
    tf32gemm_kernel<<<dim3(32, 16, 1), blk, GEMM_SMEM>>>(
        ubuf, w1, nullptr, nullptr, w1b, h1, nullptr, nullptr,
        ROWS_X, FFDIM, DMODEL, 1);
    tf32gemm_kernel<<<dim3(8, 16, 1), blk, GEMM_SMEM>>>(
        h1, w2, nullptr, nullptr, w2b, tbuf, nullptr, nullptr,
        ROWS_X, DMODEL, FFDIM, 0);
    ln_kernel<<<ROWS_X, blk>>>(tbuf, ubuf, ln2g, ln2b, out);
}